// round 15
// baseline (speedup 1.0000x reference)
#include <cuda_runtime.h>
#include <cuda_fp16.h>
#include <math_constants.h>
#include <cstdint>

// Problem constants
#define BATCH  4
#define LEN    1024
#define DMODEL 1024
#define HEADS  16
#define HDIM   64
// scale * log2(e):  (1/32) * 1.4426950408889634
#define SL2E   0.04508422002778011f

#define NK (BATCH * LEN * DMODEL)     // 4194304
#define NW (DMODEL * DMODEL)          // 1048576

// Attention: 128 q-rows per block, 8 warps x 16 rows, K/V tile 32,
// 4-deep ring with S computed one tile ahead (S/PV overlap).
#define TQ 128
#define TK 32
#define NT (LEN / TK)
#define A_SV 9216                     // half units: sK = 4*32*72 = 9216
#define ATTN_SMEM (18432 * 2)         // 36864 B

// Projection: 128x128 tile, BK=32, 8 warps (2m x 4n), warp tile 64x32, 3-stage
#define PBK 32
#define P_SB 15360                    // 3*128*40 halves per array
#define PROJ_SMEM (2 * 15360 * 2)     // 61440 B

// fp16 mirrors (device globals; allocs forbidden)
__device__ __half g_K16[NK];
__device__ __half g_V16[NK];
__device__ __half g_W16[NW];
__device__ __half g_O16[NK];

// ---- helpers -------------------------------------------------------------

__device__ __forceinline__ float ex2f(float x) {
    float y;
    asm("ex2.approx.ftz.f32 %0, %1;" : "=f"(y) : "f"(x));
    return y;
}

__device__ __forceinline__ void mma_f16(float c[4],
                                        uint32_t a0, uint32_t a1, uint32_t a2, uint32_t a3,
                                        uint32_t b0, uint32_t b1) {
    asm volatile(
        "mma.sync.aligned.m16n8k16.row.col.f32.f16.f16.f32 "
        "{%0,%1,%2,%3}, {%4,%5,%6,%7}, {%8,%9}, {%0,%1,%2,%3};"
        : "+f"(c[0]), "+f"(c[1]), "+f"(c[2]), "+f"(c[3])
        : "r"(a0), "r"(a1), "r"(a2), "r"(a3), "r"(b0), "r"(b1));
}

__device__ __forceinline__ void ldsm_x4(uint32_t& r0, uint32_t& r1,
                                        uint32_t& r2, uint32_t& r3,
                                        const __half* p) {
    uint32_t addr = (uint32_t)__cvta_generic_to_shared(p);
    asm volatile("ldmatrix.sync.aligned.m8n8.x4.shared.b16 {%0,%1,%2,%3}, [%4];"
                 : "=r"(r0), "=r"(r1), "=r"(r2), "=r"(r3) : "r"(addr));
}
__device__ __forceinline__ void ldsm_x4t(uint32_t& r0, uint32_t& r1,
                                         uint32_t& r2, uint32_t& r3,
                                         const __half* p) {
    uint32_t addr = (uint32_t)__cvta_generic_to_shared(p);
    asm volatile("ldmatrix.sync.aligned.m8n8.x4.trans.shared.b16 {%0,%1,%2,%3}, [%4];"
                 : "=r"(r0), "=r"(r1), "=r"(r2), "=r"(r3) : "r"(addr));
}

__device__ __forceinline__ void cp16(__half* sdst, const __half* gsrc) {
    uint32_t d = (uint32_t)__cvta_generic_to_shared(sdst);
    asm volatile("cp.async.cg.shared.global [%0], [%1], 16;" :: "r"(d), "l"(gsrc));
}
#define CP_COMMIT() asm volatile("cp.async.commit_group;")
#define CP_WAIT1()  asm volatile("cp.async.wait_group 1;")
#define CP_WAIT2()  asm volatile("cp.async.wait_group 2;")

__device__ __forceinline__ uint32_t packh2(float a, float b) {
    __half2 h = __floats2half2_rn(a, b);
    return *reinterpret_cast<uint32_t*>(&h);
}

#define CVTH4(dst, v4)                                              \
    {   __half2* _d = reinterpret_cast<__half2*>(dst);              \
        _d[0] = __floats2half2_rn(v4.x, v4.y);                      \
        _d[1] = __floats2half2_rn(v4.z, v4.w);  }

extern __shared__ __half dsm[];

// ---------------------------------------------------------------------------
// fp32 -> fp16 pre-conversion: K+V on main stream, W on stream 2
// ---------------------------------------------------------------------------
__global__ __launch_bounds__(256)
void cvtKV_kernel(const float* __restrict__ K,
                  const float* __restrict__ V)
{
    const size_t i = ((size_t)blockIdx.x * 256 + threadIdx.x) * 8;
    const float* src;
    __half* dst;
    size_t off;
    if (i < NK) { src = K; dst = g_K16; off = i; }
    else        { src = V; dst = g_V16; off = i - NK; }
    float4 a = *reinterpret_cast<const float4*>(src + off);
    float4 b = *reinterpret_cast<const float4*>(src + off + 4);
    __half2 h[4] = { __floats2half2_rn(a.x, a.y), __floats2half2_rn(a.z, a.w),
                     __floats2half2_rn(b.x, b.y), __floats2half2_rn(b.z, b.w) };
    *reinterpret_cast<uint4*>(dst + off) = *reinterpret_cast<uint4*>(h);
}

__global__ __launch_bounds__(256)
void cvtW_kernel(const float* __restrict__ W)
{
    const size_t off = ((size_t)blockIdx.x * 256 + threadIdx.x) * 8;
    float4 a = *reinterpret_cast<const float4*>(W + off);
    float4 b = *reinterpret_cast<const float4*>(W + off + 4);
    __half2 h[4] = { __floats2half2_rn(a.x, a.y), __floats2half2_rn(a.z, a.w),
                     __floats2half2_rn(b.x, b.y), __floats2half2_rn(b.z, b.w) };
    *reinterpret_cast<uint4*>(g_W16 + off) = *reinterpret_cast<uint4*>(h);
}

// ---------------------------------------------------------------------------
// Flash-style attention (one batch per launch): fp16 mma.sync, 8 warps x 16
// q-rows, P in registers, SL2E folded into Q, 4-deep cp.async ring,
// S computed one tile ahead. Grid (8 qblocks, 16 heads), 256 threads.
// ---------------------------------------------------------------------------
__global__ __launch_bounds__(256, 2)
void attn_kernel(const float* __restrict__ Q, int b)
{
    __half (*sK)[TK][72] = reinterpret_cast<__half(*)[TK][72]>(dsm);
    __half (*sV)[TK][72] = reinterpret_cast<__half(*)[TK][72]>(dsm + A_SV);

    const int t    = threadIdx.x;
    const int lane = t & 31;
    const int wid  = t >> 5;          // 0..7
    const int g    = lane >> 2;
    const int tig  = lane & 3;
    const int warpM = wid * 16;       // 16 q-rows per warp

    const int h  = blockIdx.y;
    const int q0 = blockIdx.x * TQ;
    const size_t base = (size_t)b * LEN * DMODEL + (size_t)h * HDIM;

    const int aRow = ((lane >> 3) & 1) * 8 + (lane & 7);   // A frags (Q) + V trans
    const int aCol = ((lane >> 4) & 1) * 8;
    const int bRow = ((lane >> 4) & 1) * 8 + (lane & 7);   // K B-frag pairs
    const int bCol = ((lane >> 3) & 1) * 8;

    // ---- stage Q*SL2E (f32->fp16) into tmp smem, lift fragments to regs ----
    __half (*tmpQ)[72] = reinterpret_cast<__half(*)[72]>(dsm);  // [128][72]
    {
        const int c = (t & 15) * 4;
        #pragma unroll
        for (int p = 0; p < 8; p++) {
            const int r = p * 16 + (t >> 4);
            float4 v4 = *reinterpret_cast<const float4*>(
                Q + base + (size_t)(q0 + r) * DMODEL + c);
            v4.x *= SL2E; v4.y *= SL2E; v4.z *= SL2E; v4.w *= SL2E;
            CVTH4((&tmpQ[r][c]), v4);
        }
    }
    __syncthreads();

    uint32_t qf[4][4];
    #pragma unroll
    for (int ks = 0; ks < 4; ks++)
        ldsm_x4(qf[ks][0], qf[ks][1], qf[ks][2], qf[ks][3],
                &tmpQ[warpM + aRow][ks * 16 + aCol]);
    __syncthreads();   // tmpQ dead; sK/sV region free for cp.async

    float o[8][4] = {};
    float ls0 = 0.f, ls1 = 0.f;
    float s[4][4];

    // cp.async staging: 8 threads/row, 1x16B each per array
    const int sr = t >> 3;          // 0..31
    const int sq = (t & 7) * 8;     // half offset 0..56
    auto stage = [&](int buf, int kt) {
        const size_t go = base + (size_t)(kt * TK + sr) * DMODEL + sq;
        cp16(&sK[buf][sr][sq], g_K16 + go);
        cp16(&sV[buf][sr][sq], g_V16 + go);
    };

    // S(kt) = (Q*SL2E) K^T from sK[buf] into s
    auto computeS = [&](int buf) {
        #pragma unroll
        for (int nt = 0; nt < 4; nt++)
            s[nt][0] = s[nt][1] = s[nt][2] = s[nt][3] = 0.f;
        #pragma unroll
        for (int ks = 0; ks < 4; ks++) {
            uint32_t b00, b01, b10, b11;
            ldsm_x4(b00, b01, b10, b11, &sK[buf][bRow][ks * 16 + bCol]);
            uint32_t b20, b21, b30, b31;
            ldsm_x4(b20, b21, b30, b31, &sK[buf][16 + bRow][ks * 16 + bCol]);
            mma_f16(s[0], qf[ks][0], qf[ks][1], qf[ks][2], qf[ks][3], b00, b01);
            mma_f16(s[1], qf[ks][0], qf[ks][1], qf[ks][2], qf[ks][3], b10, b11);
            mma_f16(s[2], qf[ks][0], qf[ks][1], qf[ks][2], qf[ks][3], b20, b21);
            mma_f16(s[3], qf[ks][0], qf[ks][1], qf[ks][2], qf[ks][3], b30, b31);
        }
    };

    stage(0, 0); CP_COMMIT();
    stage(1, 1); CP_COMMIT();
    stage(2, 2); CP_COMMIT();

    CP_WAIT2();            // group 0 complete
    __syncthreads();
    computeS(0);           // prologue: S(0)

    for (int kt = 0; kt < NT; kt++) {
        // ---- softmax on S(kt): p = 2^s ; pack into A-fragments ----
        uint32_t pa[4], pb[4];
        #pragma unroll
        for (int nt = 0; nt < 4; nt++) {
            float p00 = ex2f(s[nt][0]);
            float p01 = ex2f(s[nt][1]);
            float p10 = ex2f(s[nt][2]);
            float p11 = ex2f(s[nt][3]);
            ls0 += p00 + p01;
            ls1 += p10 + p11;
            pa[nt] = packh2(p00, p01);
            pb[nt] = packh2(p10, p11);
        }

        CP_WAIT1();          // tile kt+1's cp.async group complete
        __syncthreads();     // all warps past PV(kt-1) -> buffer (kt+3)&3 free
        if (kt + 3 < NT) stage((kt + 3) & 3, kt + 3);
        CP_COMMIT();

        // ---- S(kt+1) and PV(kt): fully independent MMA sets ----
        if (kt + 1 < NT) computeS((kt + 1) & 3);

        const int vbuf = kt & 3;
        #pragma unroll
        for (int j = 0; j < 2; j++) {          // k chunks of 16
            #pragma unroll
            for (int v = 0; v < 4; v++) {      // 16 d-cols per v
                uint32_t v0, v1, v2, v3;
                ldsm_x4t(v0, v1, v2, v3, &sV[vbuf][j * 16 + aRow][v * 16 + aCol]);
                mma_f16(o[2 * v    ], pa[2 * j], pb[2 * j],
                        pa[2 * j + 1], pb[2 * j + 1], v0, v1);
                mma_f16(o[2 * v + 1], pa[2 * j], pb[2 * j],
                        pa[2 * j + 1], pb[2 * j + 1], v2, v3);
            }
        }
    }

    // ---- final row-sum reduce (lanes sharing g: xor 1,2), write fp16 ----
    ls0 += __shfl_xor_sync(0xffffffffu, ls0, 1);
    ls0 += __shfl_xor_sync(0xffffffffu, ls0, 2);
    ls1 += __shfl_xor_sync(0xffffffffu, ls1, 1);
    ls1 += __shfl_xor_sync(0xffffffffu, ls1, 2);
    const float inv0 = 1.0f / ls0, inv1 = 1.0f / ls1;

    #pragma unroll
    for (int nt = 0; nt < 8; nt++) {
        const int col = nt * 8 + 2 * tig;
        *reinterpret_cast<__half2*>(
            &g_O16[base + (size_t)(q0 + warpM + g) * DMODEL + col]) =
            __floats2half2_rn(o[nt][0] * inv0, o[nt][1] * inv0);
        *reinterpret_cast<__half2*>(
            &g_O16[base + (size_t)(q0 + warpM + g + 8) * DMODEL + col]) =
            __floats2half2_rn(o[nt][2] * inv1, o[nt][3] * inv1);
    }
}

// ---------------------------------------------------------------------------
// Projection chunk: out = g_O16 @ g_W16^T + bias over 8 row-blocks.
// 128x128 tile, BK=32, 8 warps (2m x 4n), warp tile 64x32, 2 CTAs/SM.
// Grid (8 ntiles, 8 rowblocks); row offset mblk0 selects the batch.
// ---------------------------------------------------------------------------
__global__ __launch_bounds__(256, 2)
void proj_kernel(const float* __restrict__ bias,
                 float* __restrict__ out, int mblk0)
{
    __half (*sA)[128][40] = reinterpret_cast<__half(*)[128][40]>(dsm);
    __half (*sB)[128][40] = reinterpret_cast<__half(*)[128][40]>(dsm + P_SB);

    const int t    = threadIdx.x;
    const int lane = t & 31;
    const int wid  = t >> 5;
    const int g    = lane >> 2;
    const int tig  = lane & 3;
    const int wm   = (wid >> 2) * 64;
    const int wn   = (wid & 3) * 32;
    const int m0   = (mblk0 + blockIdx.y) * 128;
    const int n0   = blockIdx.x * 128;

    const int aRow = ((lane >> 3) & 1) * 8 + (lane & 7);
    const int aCol = ((lane >> 4) & 1) * 8;
    const int bRow = ((lane >> 4) & 1) * 8 + (lane & 7);
    const int bCol = ((lane >> 3) & 1) * 8;

    // cp.async staging: 2 threads/row, 2x16B each
    const int sr = t >> 1;          // 0..127
    const int sq = (t & 1) * 16;    // half offset
    auto stage = [&](int buf, int k0) {
        const __half* ap = g_O16 + (size_t)(m0 + sr) * DMODEL + k0 + sq;
        const __half* bp = g_W16 + (size_t)(n0 + sr) * DMODEL + k0 + sq;
        cp16(&sA[buf][sr][sq], ap);
        cp16(&sA[buf][sr][sq + 8], ap + 8);
        cp16(&sB[buf][sr][sq], bp);
        cp16(&sB[buf][sr][sq + 8], bp + 8);
    };

    float acc[4][4][4] = {};

    stage(0, 0);      CP_COMMIT();
    stage(1, PBK);    CP_COMMIT();

    const int NITER = DMODEL / PBK;   // 32
    for (int i = 0; i < NITER; i++) {
        CP_WAIT1();
        __syncthreads();
        if (i + 2 < NITER) stage((i + 2) % 3, (i + 2) * PBK);
        CP_COMMIT();

        const int buf = i % 3;

        #pragma unroll
        for (int kk = 0; kk < PBK; kk += 16) {
            uint32_t a[4][4];
            #pragma unroll
            for (int mt = 0; mt < 4; mt++)
                ldsm_x4(a[mt][0], a[mt][1], a[mt][2], a[mt][3],
                        &sA[buf][wm + mt * 16 + aRow][kk + aCol]);

            uint32_t bf[4][2];
            #pragma unroll
            for (int np = 0; np < 2; np++)
                ldsm_x4(bf[np * 2][0], bf[np * 2][1], bf[np * 2 + 1][0], bf[np * 2 + 1][1],
                        &sB[buf][wn + np * 16 + bRow][kk + bCol]);

            #pragma unroll
            for (int nt = 0; nt < 4; nt++)
                #pragma unroll
                for (int mt = 0; mt < 4; mt++)
                    mma_f16(acc[mt][nt], a[mt][0], a[mt][1], a[mt][2], a[mt][3],
                            bf[nt][0], bf[nt][1]);
        }
    }

    // ---- epilogue with bias ----
    #pragma unroll
    for (int mt = 0; mt < 4; mt++) {
        const int row = m0 + wm + mt * 16 + g;
        #pragma unroll
        for (int nt = 0; nt < 4; nt++) {
            const int col = n0 + wn + nt * 8 + 2 * tig;
            const float b0v = bias[col], b1v = bias[col + 1];
            *reinterpret_cast<float2*>(out + (size_t)row * DMODEL + col) =
                make_float2(acc[mt][nt][0] + b0v, acc[mt][nt][1] + b1v);
            *reinterpret_cast<float2*>(out + (size_t)(row + 8) * DMODEL + col) =
                make_float2(acc[mt][nt][2] + b0v, acc[mt][nt][3] + b1v);
        }
    }
}

// ---------------------------------------------------------------------------
// Two-lane graph: stream0: cvtKV -> A0 -> A1 -> A2 -> A3
//                 stream2: cvtW -> P0 -> P1 -> P2 -> P3 (Pb waits Ab)
// ---------------------------------------------------------------------------
extern "C" void kernel_launch(void* const* d_in, const int* in_sizes, int n_in,
                              void* d_out, int out_size)
{
    const float* Q  = (const float*)d_in[0];
    const float* K  = (const float*)d_in[1];
    const float* V  = (const float*)d_in[2];
    const float* W  = (const float*)d_in[3];
    const float* bi = (const float*)d_in[4];
    float* out = (float*)d_out;

    static cudaStream_t s2 = nullptr;
    static cudaEvent_t evRoot, evA[BATCH], evP;
    if (s2 == nullptr) {
        cudaStreamCreateWithFlags(&s2, cudaStreamNonBlocking);
        cudaEventCreateWithFlags(&evRoot, cudaEventDisableTiming);
        for (int i = 0; i < BATCH; i++)
            cudaEventCreateWithFlags(&evA[i], cudaEventDisableTiming);
        cudaEventCreateWithFlags(&evP, cudaEventDisableTiming);
    }

    cudaFuncSetAttribute(attn_kernel,
                         cudaFuncAttributeMaxDynamicSharedMemorySize, ATTN_SMEM);
    cudaFuncSetAttribute(proj_kernel,
                         cudaFuncAttributeMaxDynamicSharedMemorySize, PROJ_SMEM);

    // fork second lane off the (possibly capturing) main stream
    cudaEventRecord(evRoot, 0);
    cudaStreamWaitEvent(s2, evRoot, 0);

    cvtW_kernel<<<NW / 8 / 256, 256, 0, s2>>>(W);          // 512 blocks
    cvtKV_kernel<<<2 * NK / 8 / 256, 256>>>(K, V);         // 4096 blocks

    for (int b = 0; b < BATCH; b++) {
        attn_kernel<<<dim3(LEN / TQ, HEADS), 256, ATTN_SMEM>>>(Q, b);
        cudaEventRecord(evA[b], 0);
        cudaStreamWaitEvent(s2, evA[b], 0);
        proj_kernel<<<dim3(DMODEL / 128, 8), 256, PROJ_SMEM, s2>>>(bi, out, b * 8);
    }

    // join second lane back into the main stream
    cudaEventRecord(evP, s2);
    cudaStreamWaitEvent(0, evP, 0);
}

// round 16
// speedup vs baseline: 1.4593x; 1.4593x over previous
#include <cuda_runtime.h>
#include <cuda_fp16.h>
#include <math_constants.h>
#include <cstdint>

// Problem constants
#define BATCH  4
#define LEN    1024
#define DMODEL 1024
#define HEADS  16
#define HDIM   64
// scale * log2(e):  (1/32) * 1.4426950408889634
#define SL2E   0.04508422002778011f

#define NK (BATCH * LEN * DMODEL)     // 4194304
#define NW (DMODEL * DMODEL)          // 1048576

// Attention: 128 q-rows per block, 8 warps x 16 rows, K/V tile 32,
// tiles processed in PAIRS (64 rows) per barrier interval, 3 pair-buffers.
#define TQ 128
#define TK 32
#define NT (LEN / TK)                 // 32 tiles
#define NP (NT / 2)                   // 16 pairs
#define A_SV 13824                    // half units: sK = 3*64*72 = 13824
#define ATTN_SMEM (27648 * 2)         // 55296 B

// Projection: 128x128 tile, BK=32, 8 warps (2m x 4n), warp tile 64x32, 3-stage
#define PBK 32
#define P_SB 15360                    // 3*128*40 halves per array
#define PROJ_SMEM (2 * 15360 * 2)     // 61440 B

// fp16 mirrors (device globals; allocs forbidden)
__device__ __half g_K16[NK];
__device__ __half g_V16[NK];
__device__ __half g_W16[NW];
__device__ __half g_O16[NK];

// ---- helpers -------------------------------------------------------------

__device__ __forceinline__ float ex2f(float x) {
    float y;
    asm("ex2.approx.ftz.f32 %0, %1;" : "=f"(y) : "f"(x));
    return y;
}

__device__ __forceinline__ void mma_f16(float c[4],
                                        uint32_t a0, uint32_t a1, uint32_t a2, uint32_t a3,
                                        uint32_t b0, uint32_t b1) {
    asm volatile(
        "mma.sync.aligned.m16n8k16.row.col.f32.f16.f16.f32 "
        "{%0,%1,%2,%3}, {%4,%5,%6,%7}, {%8,%9}, {%0,%1,%2,%3};"
        : "+f"(c[0]), "+f"(c[1]), "+f"(c[2]), "+f"(c[3])
        : "r"(a0), "r"(a1), "r"(a2), "r"(a3), "r"(b0), "r"(b1));
}

__device__ __forceinline__ void ldsm_x4(uint32_t& r0, uint32_t& r1,
                                        uint32_t& r2, uint32_t& r3,
                                        const __half* p) {
    uint32_t addr = (uint32_t)__cvta_generic_to_shared(p);
    asm volatile("ldmatrix.sync.aligned.m8n8.x4.shared.b16 {%0,%1,%2,%3}, [%4];"
                 : "=r"(r0), "=r"(r1), "=r"(r2), "=r"(r3) : "r"(addr));
}
__device__ __forceinline__ void ldsm_x4t(uint32_t& r0, uint32_t& r1,
                                         uint32_t& r2, uint32_t& r3,
                                         const __half* p) {
    uint32_t addr = (uint32_t)__cvta_generic_to_shared(p);
    asm volatile("ldmatrix.sync.aligned.m8n8.x4.trans.shared.b16 {%0,%1,%2,%3}, [%4];"
                 : "=r"(r0), "=r"(r1), "=r"(r2), "=r"(r3) : "r"(addr));
}

__device__ __forceinline__ void cp16(__half* sdst, const __half* gsrc) {
    uint32_t d = (uint32_t)__cvta_generic_to_shared(sdst);
    asm volatile("cp.async.cg.shared.global [%0], [%1], 16;" :: "r"(d), "l"(gsrc));
}
#define CP_COMMIT() asm volatile("cp.async.commit_group;")
#define CP_WAIT1()  asm volatile("cp.async.wait_group 1;")

__device__ __forceinline__ uint32_t packh2(float a, float b) {
    __half2 h = __floats2half2_rn(a, b);
    return *reinterpret_cast<uint32_t*>(&h);
}

#define CVTH4(dst, v4)                                              \
    {   __half2* _d = reinterpret_cast<__half2*>(dst);              \
        _d[0] = __floats2half2_rn(v4.x, v4.y);                      \
        _d[1] = __floats2half2_rn(v4.z, v4.w);  }

extern __shared__ __half dsm[];

// ---------------------------------------------------------------------------
// fp32 -> fp16 pre-conversion for K, V, W: 16 elems/thread, 4 indep loads
// ---------------------------------------------------------------------------
__global__ __launch_bounds__(256)
void cvt16_kernel(const float* __restrict__ K,
                  const float* __restrict__ V,
                  const float* __restrict__ W)
{
    const size_t i = ((size_t)blockIdx.x * 256 + threadIdx.x) * 16;
    const float* src;
    __half* dst;
    size_t off;
    if (i < NK)            { src = K; dst = g_K16; off = i; }
    else if (i < 2 * (size_t)NK) { src = V; dst = g_V16; off = i - NK; }
    else {
        off = i - 2 * (size_t)NK;
        if (off >= NW) return;
        src = W; dst = g_W16;
    }
    float4 a0 = *reinterpret_cast<const float4*>(src + off);
    float4 a1 = *reinterpret_cast<const float4*>(src + off + 4);
    float4 a2 = *reinterpret_cast<const float4*>(src + off + 8);
    float4 a3 = *reinterpret_cast<const float4*>(src + off + 12);
    __half2 h0[4] = { __floats2half2_rn(a0.x, a0.y), __floats2half2_rn(a0.z, a0.w),
                      __floats2half2_rn(a1.x, a1.y), __floats2half2_rn(a1.z, a1.w) };
    __half2 h1[4] = { __floats2half2_rn(a2.x, a2.y), __floats2half2_rn(a2.z, a2.w),
                      __floats2half2_rn(a3.x, a3.y), __floats2half2_rn(a3.z, a3.w) };
    *reinterpret_cast<uint4*>(dst + off)     = *reinterpret_cast<uint4*>(h0);
    *reinterpret_cast<uint4*>(dst + off + 8) = *reinterpret_cast<uint4*>(h1);
}

// ---------------------------------------------------------------------------
// Flash-style attention: fp16 mma.sync, 8 warps x 16 q-rows, P in registers,
// SL2E folded into Q, K/V tile-PAIRS per barrier (3 pair-buffers), S one
// tile ahead. Block = (b,h,128 q rows), 256 threads.
// ---------------------------------------------------------------------------
__global__ __launch_bounds__(256, 2)
void attn_kernel(const float* __restrict__ Q)
{
    __half (*sK)[64][72] = reinterpret_cast<__half(*)[64][72]>(dsm);
    __half (*sV)[64][72] = reinterpret_cast<__half(*)[64][72]>(dsm + A_SV);

    const int t    = threadIdx.x;
    const int lane = t & 31;
    const int wid  = t >> 5;          // 0..7
    const int g    = lane >> 2;
    const int tig  = lane & 3;
    const int warpM = wid * 16;       // 16 q-rows per warp

    const int b  = blockIdx.z;
    const int h  = blockIdx.y;
    const int q0 = blockIdx.x * TQ;
    const size_t base = (size_t)b * LEN * DMODEL + (size_t)h * HDIM;

    const int aRow = ((lane >> 3) & 1) * 8 + (lane & 7);   // A frags (Q) + V trans
    const int aCol = ((lane >> 4) & 1) * 8;
    const int bRow = ((lane >> 4) & 1) * 8 + (lane & 7);   // K B-frag pairs
    const int bCol = ((lane >> 3) & 1) * 8;

    // ---- stage Q*SL2E (f32->fp16) into tmp smem, lift fragments to regs ----
    __half (*tmpQ)[72] = reinterpret_cast<__half(*)[72]>(dsm);  // [128][72]
    {
        const int c = (t & 15) * 4;
        #pragma unroll
        for (int p = 0; p < 8; p++) {
            const int r = p * 16 + (t >> 4);
            float4 v4 = *reinterpret_cast<const float4*>(
                Q + base + (size_t)(q0 + r) * DMODEL + c);
            v4.x *= SL2E; v4.y *= SL2E; v4.z *= SL2E; v4.w *= SL2E;
            CVTH4((&tmpQ[r][c]), v4);
        }
    }
    __syncthreads();

    uint32_t qf[4][4];
    #pragma unroll
    for (int ks = 0; ks < 4; ks++)
        ldsm_x4(qf[ks][0], qf[ks][1], qf[ks][2], qf[ks][3],
                &tmpQ[warpM + aRow][ks * 16 + aCol]);
    __syncthreads();   // tmpQ dead; sK/sV region free for cp.async

    float o[8][4] = {};
    float ls0 = 0.f, ls1 = 0.f;
    float s[4][4];

    // pair staging: 64 rows, 8 threads/row, each thread rows sr and sr+32
    const int sr = t >> 3;          // 0..31
    const int sq = (t & 7) * 8;     // half offset 0..56
    auto stagePair = [&](int buf, int pp) {
        const size_t g0 = base + (size_t)(pp * 64 + sr) * DMODEL + sq;
        const size_t g1 = g0 + (size_t)32 * DMODEL;
        cp16(&sK[buf][sr][sq],      g_K16 + g0);
        cp16(&sK[buf][sr + 32][sq], g_K16 + g1);
        cp16(&sV[buf][sr][sq],      g_V16 + g0);
        cp16(&sV[buf][sr + 32][sq], g_V16 + g1);
    };

    // S(tile) from sK[buf] at local row offset loff
    auto computeS = [&](int buf, int loff) {
        #pragma unroll
        for (int nt = 0; nt < 4; nt++)
            s[nt][0] = s[nt][1] = s[nt][2] = s[nt][3] = 0.f;
        #pragma unroll
        for (int ks = 0; ks < 4; ks++) {
            uint32_t b00, b01, b10, b11;
            ldsm_x4(b00, b01, b10, b11, &sK[buf][loff + bRow][ks * 16 + bCol]);
            uint32_t b20, b21, b30, b31;
            ldsm_x4(b20, b21, b30, b31, &sK[buf][loff + 16 + bRow][ks * 16 + bCol]);
            mma_f16(s[0], qf[ks][0], qf[ks][1], qf[ks][2], qf[ks][3], b00, b01);
            mma_f16(s[1], qf[ks][0], qf[ks][1], qf[ks][2], qf[ks][3], b10, b11);
            mma_f16(s[2], qf[ks][0], qf[ks][1], qf[ks][2], qf[ks][3], b20, b21);
            mma_f16(s[3], qf[ks][0], qf[ks][1], qf[ks][2], qf[ks][3], b30, b31);
        }
    };

    uint32_t pa[4], pb[4];
    auto softmaxS = [&]() {
        #pragma unroll
        for (int nt = 0; nt < 4; nt++) {
            float p00 = ex2f(s[nt][0]);
            float p01 = ex2f(s[nt][1]);
            float p10 = ex2f(s[nt][2]);
            float p11 = ex2f(s[nt][3]);
            ls0 += p00 + p01;
            ls1 += p10 + p11;
            pa[nt] = packh2(p00, p01);
            pb[nt] = packh2(p10, p11);
        }
    };
    auto pvTile = [&](int buf, int loff) {
        #pragma unroll
        for (int j = 0; j < 2; j++) {          // k chunks of 16
            #pragma unroll
            for (int v = 0; v < 4; v++) {      // 16 d-cols per v
                uint32_t v0, v1, v2, v3;
                ldsm_x4t(v0, v1, v2, v3,
                         &sV[buf][loff + j * 16 + aRow][v * 16 + aCol]);
                mma_f16(o[2 * v    ], pa[2 * j], pb[2 * j],
                        pa[2 * j + 1], pb[2 * j + 1], v0, v1);
                mma_f16(o[2 * v + 1], pa[2 * j], pb[2 * j],
                        pa[2 * j + 1], pb[2 * j + 1], v2, v3);
            }
        }
    };

    stagePair(0, 0); CP_COMMIT();
    stagePair(1, 1); CP_COMMIT();

    CP_WAIT1();            // pair 0 complete (pair 1 in flight)
    __syncthreads();
    computeS(0, 0);        // prologue: S(tile 0)

    for (int p = 0; p < NP; p++) {
        const int buf  = p % 3;
        const int nbuf = (p + 1) % 3;

        softmaxS();                         // P(2p) from s
        __syncthreads();                    // pair p-1 buffer fully consumed
        if (p + 2 < NP) stagePair((p + 2) % 3, p + 2);
        CP_COMMIT();
        CP_WAIT1();                         // pair p+1 resident (p+2 in flight)

        computeS(buf, 32);                  // S(2p+1), independent of PV below
        pvTile(buf, 0);                     // O += P(2p) V(2p)

        softmaxS();                         // P(2p+1)
        if (p + 1 < NP) computeS(nbuf, 0);  // S(2p+2), independent of PV below
        pvTile(buf, 32);                    // O += P(2p+1) V(2p+1)
    }

    // ---- final row-sum reduce (lanes sharing g: xor 1,2), write fp16 ----
    ls0 += __shfl_xor_sync(0xffffffffu, ls0, 1);
    ls0 += __shfl_xor_sync(0xffffffffu, ls0, 2);
    ls1 += __shfl_xor_sync(0xffffffffu, ls1, 1);
    ls1 += __shfl_xor_sync(0xffffffffu, ls1, 2);
    const float inv0 = 1.0f / ls0, inv1 = 1.0f / ls1;

    #pragma unroll
    for (int nt = 0; nt < 8; nt++) {
        const int col = nt * 8 + 2 * tig;
        *reinterpret_cast<__half2*>(
            &g_O16[base + (size_t)(q0 + warpM + g) * DMODEL + col]) =
            __floats2half2_rn(o[nt][0] * inv0, o[nt][1] * inv0);
        *reinterpret_cast<__half2*>(
            &g_O16[base + (size_t)(q0 + warpM + g + 8) * DMODEL + col]) =
            __floats2half2_rn(o[nt][2] * inv1, o[nt][3] * inv1);
    }
}

// ---------------------------------------------------------------------------
// Projection: out = g_O16 @ g_W16^T + bias, fp16 MMA, cp.async 3-stage pipe.
// 128x128 tile, BK=32, 8 warps (2m x 4n), warp tile 64x32, 2 CTAs/SM.
// ---------------------------------------------------------------------------
__global__ __launch_bounds__(256, 2)
void proj_kernel(const float* __restrict__ bias,
                 float* __restrict__ out)
{
    __half (*sA)[128][40] = reinterpret_cast<__half(*)[128][40]>(dsm);
    __half (*sB)[128][40] = reinterpret_cast<__half(*)[128][40]>(dsm + P_SB);

    const int t    = threadIdx.x;
    const int lane = t & 31;
    const int wid  = t >> 5;
    const int g    = lane >> 2;
    const int tig  = lane & 3;
    const int wm   = (wid >> 2) * 64;
    const int wn   = (wid & 3) * 32;
    const int m0   = blockIdx.y * 128;
    const int n0   = blockIdx.x * 128;

    const int aRow = ((lane >> 3) & 1) * 8 + (lane & 7);
    const int aCol = ((lane >> 4) & 1) * 8;
    const int bRow = ((lane >> 4) & 1) * 8 + (lane & 7);
    const int bCol = ((lane >> 3) & 1) * 8;

    // cp.async staging: 2 threads/row, 2x16B each
    const int sr = t >> 1;          // 0..127
    const int sq = (t & 1) * 16;    // half offset
    auto stage = [&](int buf, int k0) {
        const __half* ap = g_O16 + (size_t)(m0 + sr) * DMODEL + k0 + sq;
        const __half* bp = g_W16 + (size_t)(n0 + sr) * DMODEL + k0 + sq;
        cp16(&sA[buf][sr][sq], ap);
        cp16(&sA[buf][sr][sq + 8], ap + 8);
        cp16(&sB[buf][sr][sq], bp);
        cp16(&sB[buf][sr][sq + 8], bp + 8);
    };

    float acc[4][4][4] = {};

    stage(0, 0);      CP_COMMIT();
    stage(1, PBK);    CP_COMMIT();

    const int NITER = DMODEL / PBK;   // 32
    for (int i = 0; i < NITER; i++) {
        CP_WAIT1();
        __syncthreads();
        if (i + 2 < NITER) stage((i + 2) % 3, (i + 2) * PBK);
        CP_COMMIT();

        const int buf = i % 3;

        #pragma unroll
        for (int kk = 0; kk < PBK; kk += 16) {
            uint32_t a[4][4];
            #pragma unroll
            for (int mt = 0; mt < 4; mt++)
                ldsm_x4(a[mt][0], a[mt][1], a[mt][2], a[mt][3],
                        &sA[buf][wm + mt * 16 + aRow][kk + aCol]);

            uint32_t bf[4][2];
            #pragma unroll
            for (int np = 0; np < 2; np++)
                ldsm_x4(bf[np * 2][0], bf[np * 2][1], bf[np * 2 + 1][0], bf[np * 2 + 1][1],
                        &sB[buf][wn + np * 16 + bRow][kk + bCol]);

            #pragma unroll
            for (int nt = 0; nt < 4; nt++)
                #pragma unroll
                for (int mt = 0; mt < 4; mt++)
                    mma_f16(acc[mt][nt], a[mt][0], a[mt][1], a[mt][2], a[mt][3],
                            bf[nt][0], bf[nt][1]);
        }
    }

    // ---- epilogue with bias ----
    #pragma unroll
    for (int mt = 0; mt < 4; mt++) {
        const int row = m0 + wm + mt * 16 + g;
        #pragma unroll
        for (int nt = 0; nt < 4; nt++) {
            const int col = n0 + wn + nt * 8 + 2 * tig;
            const float b0v = bias[col], b1v = bias[col + 1];
            *reinterpret_cast<float2*>(out + (size_t)row * DMODEL + col) =
                make_float2(acc[mt][nt][0] + b0v, acc[mt][nt][1] + b1v);
            *reinterpret_cast<float2*>(out + (size_t)(row + 8) * DMODEL + col) =
                make_float2(acc[mt][nt][2] + b0v, acc[mt][nt][3] + b1v);
        }
    }
}

// ---------------------------------------------------------------------------
extern "C" void kernel_launch(void* const* d_in, const int* in_sizes, int n_in,
                              void* d_out, int out_size)
{
    const float* Q  = (const float*)d_in[0];
    const float* K  = (const float*)d_in[1];
    const float* V  = (const float*)d_in[2];
    const float* W  = (const float*)d_in[3];
    const float* bi = (const float*)d_in[4];
    float* out = (float*)d_out;

    cudaFuncSetAttribute(attn_kernel,
                         cudaFuncAttributeMaxDynamicSharedMemorySize, ATTN_SMEM);
    cudaFuncSetAttribute(proj_kernel,
                         cudaFuncAttributeMaxDynamicSharedMemorySize, PROJ_SMEM);

    const int ncvt = (2 * NK + NW) / 16 / 256;   // 2304 blocks
    cvt16_kernel<<<ncvt, 256>>>(K, V, W);

    dim3 agrid(LEN / TQ, HEADS, BATCH);
    attn_kernel<<<agrid, 256, ATTN_SMEM>>>(Q);

    dim3 pgrid(DMODEL / 128, (BATCH * LEN) / 128);
    proj_kernel<<<pgrid, 256, PROJ_SMEM>>>(bi, out);
}

// round 17
// speedup vs baseline: 1.4900x; 1.0210x over previous
#include <cuda_runtime.h>
#include <cuda_fp16.h>
#include <math_constants.h>
#include <cstdint>

// Problem constants
#define BATCH  4
#define LEN    1024
#define DMODEL 1024
#define HEADS  16
#define HDIM   64
// scale * log2(e):  (1/32) * 1.4426950408889634
#define SL2E   0.04508422002778011f

#define NK (BATCH * LEN * DMODEL)     // 4194304
#define NW (DMODEL * DMODEL)          // 1048576

// Attention: 128 q-rows per block, 8 warps x 16 rows, K/V tile 32,
// 4-deep ring with S computed one tile ahead (S/PV overlap).
#define TQ 128
#define TK 32
#define NT (LEN / TK)
#define A_SV 9216                     // half units: sK = 4*32*72 = 9216
#define ATTN_SMEM (18432 * 2)         // 36864 B

// Projection: 128x128 tile, BK=32, 8 warps (2m x 4n), warp tile 64x32, 3-stage
#define PBK 32
#define P_SB 15360                    // 3*128*40 halves per array
#define PROJ_SMEM (2 * 15360 * 2)     // 61440 B

// fp16 mirrors (device globals; allocs forbidden)
__device__ __half g_K16[NK];
__device__ __half g_V16[NK];
__device__ __half g_W16[NW];
__device__ __half g_O16[NK];

// ---- helpers -------------------------------------------------------------

__device__ __forceinline__ float ex2f(float x) {
    float y;
    asm("ex2.approx.ftz.f32 %0, %1;" : "=f"(y) : "f"(x));
    return y;
}

__device__ __forceinline__ void mma_f16(float c[4],
                                        uint32_t a0, uint32_t a1, uint32_t a2, uint32_t a3,
                                        uint32_t b0, uint32_t b1) {
    asm volatile(
        "mma.sync.aligned.m16n8k16.row.col.f32.f16.f16.f32 "
        "{%0,%1,%2,%3}, {%4,%5,%6,%7}, {%8,%9}, {%0,%1,%2,%3};"
        : "+f"(c[0]), "+f"(c[1]), "+f"(c[2]), "+f"(c[3])
        : "r"(a0), "r"(a1), "r"(a2), "r"(a3), "r"(b0), "r"(b1));
}

__device__ __forceinline__ void ldsm_x4(uint32_t& r0, uint32_t& r1,
                                        uint32_t& r2, uint32_t& r3,
                                        const __half* p) {
    uint32_t addr = (uint32_t)__cvta_generic_to_shared(p);
    asm volatile("ldmatrix.sync.aligned.m8n8.x4.shared.b16 {%0,%1,%2,%3}, [%4];"
                 : "=r"(r0), "=r"(r1), "=r"(r2), "=r"(r3) : "r"(addr));
}
__device__ __forceinline__ void ldsm_x4t(uint32_t& r0, uint32_t& r1,
                                         uint32_t& r2, uint32_t& r3,
                                         const __half* p) {
    uint32_t addr = (uint32_t)__cvta_generic_to_shared(p);
    asm volatile("ldmatrix.sync.aligned.m8n8.x4.trans.shared.b16 {%0,%1,%2,%3}, [%4];"
                 : "=r"(r0), "=r"(r1), "=r"(r2), "=r"(r3) : "r"(addr));
}

__device__ __forceinline__ void cp16(__half* sdst, const __half* gsrc) {
    uint32_t d = (uint32_t)__cvta_generic_to_shared(sdst);
    asm volatile("cp.async.cg.shared.global [%0], [%1], 16;" :: "r"(d), "l"(gsrc));
}
#define CP_COMMIT() asm volatile("cp.async.commit_group;")
#define CP_WAIT1()  asm volatile("cp.async.wait_group 1;")
#define CP_WAIT2()  asm volatile("cp.async.wait_group 2;")

__device__ __forceinline__ uint32_t packh2(float a, float b) {
    __half2 h = __floats2half2_rn(a, b);
    return *reinterpret_cast<uint32_t*>(&h);
}

// PDL: wait for the previous kernel's output to be visible
__device__ __forceinline__ void grid_dep_sync() {
    asm volatile("griddepcontrol.wait;" ::: "memory");
}

#define CVTH4(dst, v4)                                              \
    {   __half2* _d = reinterpret_cast<__half2*>(dst);              \
        _d[0] = __floats2half2_rn(v4.x, v4.y);                      \
        _d[1] = __floats2half2_rn(v4.z, v4.w);  }

extern __shared__ __half dsm[];

// ---------------------------------------------------------------------------
// fp32 -> fp16 pre-conversion for K, V, W  (8 elems/thread — fastest variant)
// ---------------------------------------------------------------------------
__global__ __launch_bounds__(256)
void cvt16_kernel(const float* __restrict__ K,
                  const float* __restrict__ V,
                  const float* __restrict__ W)
{
    const size_t i = ((size_t)blockIdx.x * 256 + threadIdx.x) * 8;
    const float* src;
    __half* dst;
    size_t off;
    if (i < NK)            { src = K; dst = g_K16; off = i; }
    else if (i < 2 * (size_t)NK) { src = V; dst = g_V16; off = i - NK; }
    else {
        off = i - 2 * (size_t)NK;
        if (off >= NW) return;
        src = W; dst = g_W16;
    }
    float4 a = *reinterpret_cast<const float4*>(src + off);
    float4 b = *reinterpret_cast<const float4*>(src + off + 4);
    __half2 h[4] = { __floats2half2_rn(a.x, a.y), __floats2half2_rn(a.z, a.w),
                     __floats2half2_rn(b.x, b.y), __floats2half2_rn(b.z, b.w) };
    *reinterpret_cast<uint4*>(dst + off) = *reinterpret_cast<uint4*>(h);
}

// ---------------------------------------------------------------------------
// Flash-style attention: fp16 mma.sync, 8 warps x 16 q-rows, P in registers,
// SL2E folded into Q, 4-deep cp.async ring, S one tile ahead. PDL: Q prologue
// runs before griddepcontrol.wait (overlaps cvt tail).
// Block = (b,h,128 q rows), 256 threads.
// ---------------------------------------------------------------------------
__global__ __launch_bounds__(256, 2)
void attn_kernel(const float* __restrict__ Q)
{
    __half (*sK)[TK][72] = reinterpret_cast<__half(*)[TK][72]>(dsm);
    __half (*sV)[TK][72] = reinterpret_cast<__half(*)[TK][72]>(dsm + A_SV);

    const int t    = threadIdx.x;
    const int lane = t & 31;
    const int wid  = t >> 5;          // 0..7
    const int g    = lane >> 2;
    const int tig  = lane & 3;
    const int warpM = wid * 16;       // 16 q-rows per warp

    const int b  = blockIdx.z;
    const int h  = blockIdx.y;
    const int q0 = blockIdx.x * TQ;
    const size_t base = (size_t)b * LEN * DMODEL + (size_t)h * HDIM;

    const int aRow = ((lane >> 3) & 1) * 8 + (lane & 7);   // A frags (Q) + V trans
    const int aCol = ((lane >> 4) & 1) * 8;
    const int bRow = ((lane >> 4) & 1) * 8 + (lane & 7);   // K B-frag pairs
    const int bCol = ((lane >> 3) & 1) * 8;

    // ---- stage Q*SL2E (f32->fp16) into tmp smem, lift fragments to regs ----
    // (reads only the kernel input Q — legal before griddepcontrol.wait)
    __half (*tmpQ)[72] = reinterpret_cast<__half(*)[72]>(dsm);  // [128][72]
    {
        const int c = (t & 15) * 4;
        #pragma unroll
        for (int p = 0; p < 8; p++) {
            const int r = p * 16 + (t >> 4);
            float4 v4 = *reinterpret_cast<const float4*>(
                Q + base + (size_t)(q0 + r) * DMODEL + c);
            v4.x *= SL2E; v4.y *= SL2E; v4.z *= SL2E; v4.w *= SL2E;
            CVTH4((&tmpQ[r][c]), v4);
        }
    }
    __syncthreads();

    uint32_t qf[4][4];
    #pragma unroll
    for (int ks = 0; ks < 4; ks++)
        ldsm_x4(qf[ks][0], qf[ks][1], qf[ks][2], qf[ks][3],
                &tmpQ[warpM + aRow][ks * 16 + aCol]);
    __syncthreads();   // tmpQ dead; sK/sV region free for cp.async

    grid_dep_sync();   // cvt output (g_K16/g_V16) now guaranteed visible

    float o[8][4] = {};
    float ls0 = 0.f, ls1 = 0.f;
    float s[4][4];

    // cp.async staging: 8 threads/row, 1x16B each per array
    const int sr = t >> 3;          // 0..31
    const int sq = (t & 7) * 8;     // half offset 0..56
    auto stage = [&](int buf, int kt) {
        const size_t go = base + (size_t)(kt * TK + sr) * DMODEL + sq;
        cp16(&sK[buf][sr][sq], g_K16 + go);
        cp16(&sV[buf][sr][sq], g_V16 + go);
    };

    // S(kt) = (Q*SL2E) K^T from sK[buf] into s
    auto computeS = [&](int buf) {
        #pragma unroll
        for (int nt = 0; nt < 4; nt++)
            s[nt][0] = s[nt][1] = s[nt][2] = s[nt][3] = 0.f;
        #pragma unroll
        for (int ks = 0; ks < 4; ks++) {
            uint32_t b00, b01, b10, b11;
            ldsm_x4(b00, b01, b10, b11, &sK[buf][bRow][ks * 16 + bCol]);
            uint32_t b20, b21, b30, b31;
            ldsm_x4(b20, b21, b30, b31, &sK[buf][16 + bRow][ks * 16 + bCol]);
            mma_f16(s[0], qf[ks][0], qf[ks][1], qf[ks][2], qf[ks][3], b00, b01);
            mma_f16(s[1], qf[ks][0], qf[ks][1], qf[ks][2], qf[ks][3], b10, b11);
            mma_f16(s[2], qf[ks][0], qf[ks][1], qf[ks][2], qf[ks][3], b20, b21);
            mma_f16(s[3], qf[ks][0], qf[ks][1], qf[ks][2], qf[ks][3], b30, b31);
        }
    };

    stage(0, 0); CP_COMMIT();
    stage(1, 1); CP_COMMIT();
    stage(2, 2); CP_COMMIT();

    CP_WAIT2();            // group 0 complete
    __syncthreads();
    computeS(0);           // prologue: S(0)

    for (int kt = 0; kt < NT; kt++) {
        // ---- softmax on S(kt): p = 2^s ; pack into A-fragments ----
        uint32_t pa[4], pb[4];
        #pragma unroll
        for (int nt = 0; nt < 4; nt++) {
            float p00 = ex2f(s[nt][0]);
            float p01 = ex2f(s[nt][1]);
            float p10 = ex2f(s[nt][2]);
            float p11 = ex2f(s[nt][3]);
            ls0 += p00 + p01;
            ls1 += p10 + p11;
            pa[nt] = packh2(p00, p01);
            pb[nt] = packh2(p10, p11);
        }

        CP_WAIT1();          // tile kt+1's cp.async group complete
        __syncthreads();     // all warps past PV(kt-1) -> buffer (kt+3)&3 free
        if (kt + 3 < NT) stage((kt + 3) & 3, kt + 3);
        CP_COMMIT();

        // ---- S(kt+1) and PV(kt): fully independent MMA sets ----
        if (kt + 1 < NT) computeS((kt + 1) & 3);

        const int vbuf = kt & 3;
        #pragma unroll
        for (int j = 0; j < 2; j++) {          // k chunks of 16
            #pragma unroll
            for (int v = 0; v < 4; v++) {      // 16 d-cols per v
                uint32_t v0, v1, v2, v3;
                ldsm_x4t(v0, v1, v2, v3, &sV[vbuf][j * 16 + aRow][v * 16 + aCol]);
                mma_f16(o[2 * v    ], pa[2 * j], pb[2 * j],
                        pa[2 * j + 1], pb[2 * j + 1], v0, v1);
                mma_f16(o[2 * v + 1], pa[2 * j], pb[2 * j],
                        pa[2 * j + 1], pb[2 * j + 1], v2, v3);
            }
        }
    }

    // ---- final row-sum reduce (lanes sharing g: xor 1,2), write fp16 ----
    ls0 += __shfl_xor_sync(0xffffffffu, ls0, 1);
    ls0 += __shfl_xor_sync(0xffffffffu, ls0, 2);
    ls1 += __shfl_xor_sync(0xffffffffu, ls1, 1);
    ls1 += __shfl_xor_sync(0xffffffffu, ls1, 2);
    const float inv0 = 1.0f / ls0, inv1 = 1.0f / ls1;

    #pragma unroll
    for (int nt = 0; nt < 8; nt++) {
        const int col = nt * 8 + 2 * tig;
        *reinterpret_cast<__half2*>(
            &g_O16[base + (size_t)(q0 + warpM + g) * DMODEL + col]) =
            __floats2half2_rn(o[nt][0] * inv0, o[nt][1] * inv0);
        *reinterpret_cast<__half2*>(
            &g_O16[base + (size_t)(q0 + warpM + g + 8) * DMODEL + col]) =
            __floats2half2_rn(o[nt][2] * inv1, o[nt][3] * inv1);
    }
}

// ---------------------------------------------------------------------------
// Projection: out = g_O16 @ g_W16^T + bias, fp16 MMA, cp.async 3-stage pipe.
// 128x128 tile, BK=32, 8 warps (2m x 4n), warp tile 64x32, 2 CTAs/SM.
// PDL: launch + setup overlap attn's tail; griddepcontrol.wait before any
// read of g_O16/g_W16.
// ---------------------------------------------------------------------------
__global__ __launch_bounds__(256, 2)
void proj_kernel(const float* __restrict__ bias,
                 float* __restrict__ out)
{
    __half (*sA)[128][40] = reinterpret_cast<__half(*)[128][40]>(dsm);
    __half (*sB)[128][40] = reinterpret_cast<__half(*)[128][40]>(dsm + P_SB);

    const int t    = threadIdx.x;
    const int lane = t & 31;
    const int wid  = t >> 5;
    const int g    = lane >> 2;
    const int tig  = lane & 3;
    const int wm   = (wid >> 2) * 64;
    const int wn   = (wid & 3) * 32;
    const int m0   = blockIdx.y * 128;
    const int n0   = blockIdx.x * 128;

    const int aRow = ((lane >> 3) & 1) * 8 + (lane & 7);
    const int aCol = ((lane >> 4) & 1) * 8;
    const int bRow = ((lane >> 4) & 1) * 8 + (lane & 7);
    const int bCol = ((lane >> 3) & 1) * 8;

    // cp.async staging: 2 threads/row, 2x16B each
    const int sr = t >> 1;          // 0..127
    const int sq = (t & 1) * 16;    // half offset
    auto stage = [&](int buf, int k0) {
        const __half* ap = g_O16 + (size_t)(m0 + sr) * DMODEL + k0 + sq;
        const __half* bp = g_W16 + (size_t)(n0 + sr) * DMODEL + k0 + sq;
        cp16(&sA[buf][sr][sq], ap);
        cp16(&sA[buf][sr][sq + 8], ap + 8);
        cp16(&sB[buf][sr][sq], bp);
        cp16(&sB[buf][sr][sq + 8], bp + 8);
    };

    float acc[4][4][4] = {};

    grid_dep_sync();   // attn output (g_O16) now guaranteed visible

    stage(0, 0);      CP_COMMIT();
    stage(1, PBK);    CP_COMMIT();

    const int NITER = DMODEL / PBK;   // 32
    for (int i = 0; i < NITER; i++) {
        CP_WAIT1();
        __syncthreads();
        if (i + 2 < NITER) stage((i + 2) % 3, (i + 2) * PBK);
        CP_COMMIT();

        const int buf = i % 3;

        #pragma unroll
        for (int kk = 0; kk < PBK; kk += 16) {
            uint32_t a[4][4];
            #pragma unroll
            for (int mt = 0; mt < 4; mt++)
                ldsm_x4(a[mt][0], a[mt][1], a[mt][2], a[mt][3],
                        &sA[buf][wm + mt * 16 + aRow][kk + aCol]);

            uint32_t bf[4][2];
            #pragma unroll
            for (int np = 0; np < 2; np++)
                ldsm_x4(bf[np * 2][0], bf[np * 2][1], bf[np * 2 + 1][0], bf[np * 2 + 1][1],
                        &sB[buf][wn + np * 16 + bRow][kk + bCol]);

            #pragma unroll
            for (int nt = 0; nt < 4; nt++)
                #pragma unroll
                for (int mt = 0; mt < 4; mt++)
                    mma_f16(acc[mt][nt], a[mt][0], a[mt][1], a[mt][2], a[mt][3],
                            bf[nt][0], bf[nt][1]);
        }
    }

    // ---- epilogue with bias ----
    #pragma unroll
    for (int mt = 0; mt < 4; mt++) {
        const int row = m0 + wm + mt * 16 + g;
        #pragma unroll
        for (int nt = 0; nt < 4; nt++) {
            const int col = n0 + wn + nt * 8 + 2 * tig;
            const float b0v = bias[col], b1v = bias[col + 1];
            *reinterpret_cast<float2*>(out + (size_t)row * DMODEL + col) =
                make_float2(acc[mt][nt][0] + b0v, acc[mt][nt][1] + b1v);
            *reinterpret_cast<float2*>(out + (size_t)(row + 8) * DMODEL + col) =
                make_float2(acc[mt][nt][2] + b0v, acc[mt][nt][3] + b1v);
        }
    }
}

// ---------------------------------------------------------------------------
extern "C" void kernel_launch(void* const* d_in, const int* in_sizes, int n_in,
                              void* d_out, int out_size)
{
    const float* Q  = (const float*)d_in[0];
    const float* K  = (const float*)d_in[1];
    const float* V  = (const float*)d_in[2];
    const float* W  = (const float*)d_in[3];
    const float* bi = (const float*)d_in[4];
    float* out = (float*)d_out;

    cudaFuncSetAttribute(attn_kernel,
                         cudaFuncAttributeMaxDynamicSharedMemorySize, ATTN_SMEM);
    cudaFuncSetAttribute(proj_kernel,
                         cudaFuncAttributeMaxDynamicSharedMemorySize, PROJ_SMEM);

    const int ncvt = (2 * NK + NW) / 8 / 256;
    cvt16_kernel<<<ncvt, 256>>>(K, V, W);

    // PDL attribute: allow next kernel to launch while predecessor drains
    cudaLaunchAttribute pdl[1];
    pdl[0].id = cudaLaunchAttributeProgrammaticStreamSerialization;
    pdl[0].val.programmaticStreamSerializationAllowed = 1;

    {
        cudaLaunchConfig_t cfg = {};
        cfg.gridDim  = dim3(LEN / TQ, HEADS, BATCH);
        cfg.blockDim = dim3(256, 1, 1);
        cfg.dynamicSmemBytes = ATTN_SMEM;
        cfg.stream = 0;
        cfg.attrs = pdl;
        cfg.numAttrs = 1;
        cudaLaunchKernelEx(&cfg, attn_kernel, Q);
    }
    {
        cudaLaunchConfig_t cfg = {};
        cfg.gridDim  = dim3(DMODEL / 128, (BATCH * LEN) / 128, 1);
        cfg.blockDim = dim3(256, 1, 1);
        cfg.dynamicSmemBytes = PROJ_SMEM;
        cfg.stream = 0;
        cfg.attrs = pdl;
        cfg.numAttrs = 1;
        cudaLaunchKernelEx(&cfg, proj_kernel, bi, out);
    }
}